// round 16
// baseline (speedup 1.0000x reference)
#include <cuda_runtime.h>
#include <cstdint>

// Problem dims (fixed by the dataset)
#define B_DIM 128
#define T_DIM 128
#define I_DIM 1024
#define O_DIM 1024
#define BT_DIM 16384          // B*T
#define BTO_SZ 16777216       // B*T*O
#define IO_SZ  1048576        // I*O

// ---------------- static device scratch (no allocations allowed) ----------------
__device__ float g_h[BTO_SZ];                       // h = x @ w    [B*T, O] fp32
__device__ float g_d[O_DIM * O_DIM];                // d = w^T w    [O, O]
__device__ float g_spk[BTO_SZ];                     // spike scratch (fallback)
__device__ float g_invn[O_DIM];                     // 1/(norm+eps)
__device__ int   g_cnt;

__device__ __forceinline__ uint32_t smem_u32(const void* p) {
    uint32_t a;
    asm("{ .reg .u64 t; cvta.to.shared.u64 t, %1; cvt.u32.u64 %0, t; }" : "=r"(a) : "l"(p));
    return a;
}
#define CP_ASYNC16(dst, src) \
    asm volatile("cp.async.cg.shared.global [%0], [%1], 16;" :: "r"(dst), "l"(src))
#define CP_COMMIT() asm volatile("cp.async.commit_group;")
#define CP_WAIT0()  asm volatile("cp.async.wait_group 0;" ::: "memory")

// ==================== h = x @ w : EXACT R8/R13 kernel (do not touch) ====================
// BITWISE CONTRACT: each output = single fp32 accumulator, IEEE FMA, k ascending.
// At the FFMA2 rt-3 banked ceiling (~680us).
__global__ void __launch_bounds__(256)
h_sgemm_kernel(const float* __restrict__ A,   // x [16384, 1024] row-major
               const float* __restrict__ B,   // w [1024, 1024]  row-major (k-major)
               float* __restrict__ C)
{
    __shared__ __align__(16) float As[2][8][132];   // [stage][k][m]
    __shared__ __align__(16) float Bs[2][8][128];   // [stage][k][n]

    const int tid  = threadIdx.x;
    const int bx   = blockIdx.x;            // N tile (8)
    const int by   = blockIdx.y;            // M tile (128)
    const int trow = tid >> 4;              // 0..15
    const int tcol = tid & 15;              // 0..15

    const int a_row = tid >> 1;
    const int a_k   = (tid & 1) * 4;
    const float* a_src = A + (size_t)(by * 128 + a_row) * I_DIM + a_k;

    const int b_k   = tid >> 5;
    const int b_col = (tid & 31) * 4;
    const float* b_src = B + (size_t)b_k * O_DIM + bx * 128 + b_col;
    const uint32_t bs_dst[2] = { smem_u32(&Bs[0][b_k][b_col]), smem_u32(&Bs[1][b_k][b_col]) };

    unsigned long long acc2[8][4];
#pragma unroll
    for (int i = 0; i < 8; ++i)
#pragma unroll
        for (int j = 0; j < 4; ++j) acc2[i][j] = 0ULL;

    float4 areg = *(const float4*)a_src;
    CP_ASYNC16(bs_dst[0], b_src);
    CP_COMMIT();
    As[0][a_k + 0][a_row] = areg.x;
    As[0][a_k + 1][a_row] = areg.y;
    As[0][a_k + 2][a_row] = areg.z;
    As[0][a_k + 3][a_row] = areg.w;
    CP_WAIT0();
    __syncthreads();

    for (int k0 = 0; k0 < I_DIM; k0 += 8) {
        const int  buf      = (k0 >> 3) & 1;
        const bool has_next = (k0 + 8) < I_DIM;
        if (has_next) {
            areg = *(const float4*)(a_src + k0 + 8);
            CP_ASYNC16(bs_dst[buf ^ 1], b_src + (size_t)(k0 + 8) * O_DIM);
        }
        CP_COMMIT();

#pragma unroll
        for (int kk = 0; kk < 8; ++kk) {
            float a[8];
            *(float4*)&a[0] = *(const float4*)&As[buf][kk][trow * 4];
            *(float4*)&a[4] = *(const float4*)&As[buf][kk][64 + trow * 4];
            const ulonglong2 b01 = *(const ulonglong2*)&Bs[buf][kk][tcol * 4];
            const ulonglong2 b23 = *(const ulonglong2*)&Bs[buf][kk][64 + tcol * 4];
            const unsigned long long b2[4] = { b01.x, b01.y, b23.x, b23.y };
#pragma unroll
            for (int i = 0; i < 8; ++i) {
                unsigned long long a2;
                asm("mov.b64 %0, {%1, %1};" : "=l"(a2) : "f"(a[i]));
#pragma unroll
                for (int j = 0; j < 4; ++j)
                    asm("fma.rn.f32x2 %0, %1, %2, %0;"
                        : "+l"(acc2[i][j]) : "l"(a2), "l"(b2[j]));
            }
        }

        if (has_next) {
            const int nb = buf ^ 1;
            As[nb][a_k + 0][a_row] = areg.x;
            As[nb][a_k + 1][a_row] = areg.y;
            As[nb][a_k + 2][a_row] = areg.z;
            As[nb][a_k + 3][a_row] = areg.w;
        }
        CP_WAIT0();
        __syncthreads();
    }

#pragma unroll
    for (int ih = 0; ih < 2; ++ih)
#pragma unroll
        for (int i = 0; i < 4; ++i) {
            const int m = by * 128 + ih * 64 + trow * 4 + i;
            float* crow = C + (size_t)m * O_DIM + bx * 128;
            const int ai = ih * 4 + i;
            *(ulonglong2*)&crow[tcol * 4]      = make_ulonglong2(acc2[ai][0], acc2[ai][1]);
            *(ulonglong2*)&crow[64 + tcol * 4] = make_ulonglong2(acc2[ai][2], acc2[ai][3]);
        }
}

// ---------------- fp32 tiled GEMM (A^T @ B), used for d = w^T w (unchanged — passed) ----------------
__global__ void sgemm_at_kernel(const float* __restrict__ A,
                                const float* __restrict__ Bm,
                                float* __restrict__ C,
                                int M, int N, int K)
{
    __shared__ float As[8][128];
    __shared__ float Bs[8][128];
    const int tid = threadIdx.x;
    const int bx = blockIdx.x, by = blockIdx.y;
    const int trow = tid / 16, tcol = tid % 16;

    float acc[8][8];
#pragma unroll
    for (int i = 0; i < 8; ++i)
#pragma unroll
        for (int j = 0; j < 8; ++j) acc[i][j] = 0.f;

    for (int k0 = 0; k0 < K; k0 += 8) {
        {
            const int kk = tid >> 5, c4 = (tid & 31) * 4;
            const float4 av = *(const float4*)&A[(size_t)(k0 + kk) * M + by * 128 + c4];
            As[kk][c4 + 0] = av.x; As[kk][c4 + 1] = av.y; As[kk][c4 + 2] = av.z; As[kk][c4 + 3] = av.w;
            const float4 bv = *(const float4*)&Bm[(size_t)(k0 + kk) * N + bx * 128 + c4];
            Bs[kk][c4 + 0] = bv.x; Bs[kk][c4 + 1] = bv.y; Bs[kk][c4 + 2] = bv.z; Bs[kk][c4 + 3] = bv.w;
        }
        __syncthreads();
#pragma unroll
        for (int kk = 0; kk < 8; ++kk) {
            float4 a0 = *(const float4*)&As[kk][trow * 8 + 0];
            float4 a1 = *(const float4*)&As[kk][trow * 8 + 4];
            float4 b0 = *(const float4*)&Bs[kk][tcol * 8 + 0];
            float4 b1 = *(const float4*)&Bs[kk][tcol * 8 + 4];
            float a[8] = {a0.x, a0.y, a0.z, a0.w, a1.x, a1.y, a1.z, a1.w};
            float b[8] = {b0.x, b0.y, b0.z, b0.w, b1.x, b1.y, b1.z, b1.w};
#pragma unroll
            for (int i = 0; i < 8; ++i)
#pragma unroll
                for (int j = 0; j < 8; ++j)
                    acc[i][j] = fmaf(a[i], b[j], acc[i][j]);
        }
        __syncthreads();
    }
#pragma unroll
    for (int i = 0; i < 8; ++i) {
        const size_t r = (size_t)(by * 128 + trow * 8 + i) * N + bx * 128 + tcol * 8;
#pragma unroll
        for (int j = 0; j < 8; j += 4)
            *(float4*)&C[r + j] = make_float4(acc[i][j], acc[i][j + 1], acc[i][j + 2], acc[i][j + 3]);
    }
}

// invnorm + counter reset folded into one launch
__global__ void invnorm_kernel()
{
    const int o = threadIdx.x;
    if (o == 0) g_cnt = 0;
    g_invn[o] = 1.0f / (g_d[(size_t)o * O_DIM + o] + 1e-8f);
}

// ---------------- fused recurrent scan: 256 thr x 4 neurons, LDG.128 gather ----------------
// Was LSU-issue bound (1536 LDG.32/SM/step @1.82cyc). Now 384 LDG.128 -> L1-BW floor.
// BITWISE: per-neuron rst chain = single fp32 accumulator, rows in ascending j
// (adds grouped per row); list globally ascending neuron index (lane-major, q minor).
__global__ void __launch_bounds__(256, 1)
scan_kernel(const float* __restrict__ beta_p,
            const float* __restrict__ b_p,
            float* __restrict__ spk_out)
{
    const int b    = blockIdx.x;
    const int tq   = threadIdx.x;          // 0..255
    const int wid  = tq >> 5;              // 0..7
    const int lane = tq & 31;
    const int o0   = tq * 4;               // 4 adjacent neurons per thread

    __shared__ __align__(16) int list[O_DIM];
    __shared__ int warp_cnt[8];

    const float  beta = beta_p[0];
    const float  ombt = 1.0f - beta;
    const float4 invn = *(const float4*)&g_invn[o0];
    const float4 bo   = *(const float4*)&b_p[o0];
    float m0 = 0.f, m1 = 0.f, m2 = 0.f, m3 = 0.f;
    int   n = 0;
    int   tot_spikes = 0;

    const float* __restrict__ hb = g_h + (size_t)b * T_DIM * O_DIM + o0;
    float* __restrict__ sb = spk_out + (size_t)b * T_DIM * O_DIM + o0;

    float4 hcur = *(const float4*)hb;      // prefetch t=0

    for (int t = 0; t < T_DIM; ++t) {
        float4 hnext = make_float4(0.f, 0.f, 0.f, 0.f);
        if (t + 1 < T_DIM) hnext = *(const float4*)(hb + (size_t)(t + 1) * O_DIM);

        // rst gather: 8 rows per batch (MLP), one LDG.128 per row per thread;
        // adds grouped per row, rows ascending -> per-neuron chains ascending.
        float r0 = 0.f, r1 = 0.f, r2 = 0.f, r3 = 0.f;
        int k = 0;
        for (; k + 8 <= n; k += 8) {
            const int4 ja = *(const int4*)&list[k];
            const int4 jb = *(const int4*)&list[k + 4];
            const float4 v0 = __ldg((const float4*)&g_d[(size_t)ja.x * O_DIM + o0]);
            const float4 v1 = __ldg((const float4*)&g_d[(size_t)ja.y * O_DIM + o0]);
            const float4 v2 = __ldg((const float4*)&g_d[(size_t)ja.z * O_DIM + o0]);
            const float4 v3 = __ldg((const float4*)&g_d[(size_t)ja.w * O_DIM + o0]);
            const float4 v4 = __ldg((const float4*)&g_d[(size_t)jb.x * O_DIM + o0]);
            const float4 v5 = __ldg((const float4*)&g_d[(size_t)jb.y * O_DIM + o0]);
            const float4 v6 = __ldg((const float4*)&g_d[(size_t)jb.z * O_DIM + o0]);
            const float4 v7 = __ldg((const float4*)&g_d[(size_t)jb.w * O_DIM + o0]);
            r0 += v0.x; r1 += v0.y; r2 += v0.z; r3 += v0.w;
            r0 += v1.x; r1 += v1.y; r2 += v1.z; r3 += v1.w;
            r0 += v2.x; r1 += v2.y; r2 += v2.z; r3 += v2.w;
            r0 += v3.x; r1 += v3.y; r2 += v3.z; r3 += v3.w;
            r0 += v4.x; r1 += v4.y; r2 += v4.z; r3 += v4.w;
            r0 += v5.x; r1 += v5.y; r2 += v5.z; r3 += v5.w;
            r0 += v6.x; r1 += v6.y; r2 += v6.z; r3 += v6.w;
            r0 += v7.x; r1 += v7.y; r2 += v7.z; r3 += v7.w;
        }
        for (; k < n; ++k) {
            const float4 v = __ldg((const float4*)&g_d[(size_t)list[k] * O_DIM + o0]);
            r0 += v.x; r1 += v.y; r2 += v.z; r3 += v.w;
        }

        m0 = (m0 - r0) * beta + hcur.x * ombt;
        m1 = (m1 - r1) * beta + hcur.y * ombt;
        m2 = (m2 - r2) * beta + hcur.z * ombt;
        m3 = (m3 - r3) * beta + hcur.w * ombt;
        hcur = hnext;

        const bool s0 = (m0 * invn.x - bo.x) > 0.0f;
        const bool s1 = (m1 * invn.y - bo.y) > 0.0f;
        const bool s2 = (m2 * invn.z - bo.z) > 0.0f;
        const bool s3 = (m3 * invn.w - bo.w) > 0.0f;
        *(float4*)(sb + (size_t)t * O_DIM) =
            make_float4(s0 ? 1.f : 0.f, s1 ? 1.f : 0.f, s2 ? 1.f : 0.f, s3 ? 1.f : 0.f);

        const unsigned q0 = __ballot_sync(0xffffffffu, s0);
        const unsigned q1 = __ballot_sync(0xffffffffu, s1);
        const unsigned q2 = __ballot_sync(0xffffffffu, s2);
        const unsigned q3 = __ballot_sync(0xffffffffu, s3);
        if (lane == 0)
            warp_cnt[wid] = __popc(q0) + __popc(q1) + __popc(q2) + __popc(q3);
        __syncthreads();   // counts visible; separates list reads from writes

        // 8-wide prefix over warp counts (in every warp, lanes 0..7 carry values)
        int x = (lane < 8) ? warp_cnt[lane] : 0;
#pragma unroll
        for (int dlt = 1; dlt < 8; dlt <<= 1) {
            int y = __shfl_up_sync(0xffffffffu, x, dlt);
            if (lane >= dlt) x += y;
        }
        const int total = __shfl_sync(0xffffffffu, x, 7);
        const int off   = (wid == 0) ? 0 : __shfl_sync(0xffffffffu, x, wid - 1);

        // neuron index = wid*128 + lane*4 + q  (lane-major, q minor -> ascending)
        const unsigned lt = (1u << lane) - 1u;
        int p = off + __popc(q0 & lt) + __popc(q1 & lt) + __popc(q2 & lt) + __popc(q3 & lt);
        if (s0) list[p++] = o0;
        if (s1) list[p++] = o0 + 1;
        if (s2) list[p++] = o0 + 2;
        if (s3) list[p]   = o0 + 3;

        n = total;
        if (tq == 0) tot_spikes += total;
        __syncthreads();   // list ready for next step
    }

    if (tq == 0) atomicAdd(&g_cnt, tot_spikes);
}

__global__ void finalize_kernel(float* out, int loss_idx)
{
    out[loss_idx] = 0.5f * (float)g_cnt / (float)BTO_SZ;
}

// ==================== host side ====================
extern "C" void kernel_launch(void* const* d_in, const int* in_sizes, int n_in,
                              void* d_out, int out_size)
{
    const float *x = nullptr, *w = nullptr, *beta = nullptr, *bvec = nullptr;
    for (int i = 0; i < n_in; ++i) {
        switch (in_sizes[i]) {
            case BTO_SZ:  x    = (const float*)d_in[i]; break;
            case IO_SZ:   w    = (const float*)d_in[i]; break;
            case 1:       beta = (const float*)d_in[i]; break;
            case O_DIM:   bvec = (const float*)d_in[i]; break;
            default: break;
        }
    }

    float* out = (float*)d_out;
    float* spk_dst;
    bool   write_loss;
    int    loss_idx = 0;
    if (out_size >= BTO_SZ + 1) {
        spk_dst = out; write_loss = true; loss_idx = BTO_SZ;
    } else if (out_size == BTO_SZ) {
        spk_dst = out; write_loss = false;
    } else {
        void* p = nullptr; cudaGetSymbolAddress(&p, g_spk);
        spk_dst = (float*)p; write_loss = true; loss_idx = (out_size > 0) ? out_size - 1 : 0;
    }

    float* h_ptr; { void* p; cudaGetSymbolAddress(&p, g_h); h_ptr = (float*)p; }
    float* d_ptr; { void* p; cudaGetSymbolAddress(&p, g_d); d_ptr = (float*)p; }

    // one-time side-stream resources (created on the first, non-captured call)
    static cudaStream_t s2 = nullptr;
    static cudaEvent_t  evA = nullptr, evB = nullptr;
    if (!s2) {
        cudaStreamCreateWithFlags(&s2, cudaStreamNonBlocking);
        cudaEventCreateWithFlags(&evA, cudaEventDisableTiming);
        cudaEventCreateWithFlags(&evB, cudaEventDisableTiming);
    }

    // fork: d = w^T w (+ invnorm/counter reset) on side stream, concurrent with h
    cudaEventRecord(evA, 0);
    cudaStreamWaitEvent(s2, evA, 0);
    {
        dim3 grid(O_DIM / 128, O_DIM / 128);    // 64 CTAs — fills h's tail waves
        sgemm_at_kernel<<<grid, 256, 0, s2>>>(w, w, d_ptr, O_DIM, O_DIM, I_DIM);
    }
    invnorm_kernel<<<1, O_DIM, 0, s2>>>();
    cudaEventRecord(evB, s2);

    // h = x @ w : EXACT R8/R13 winner (FFMA2 ceiling), main stream
    {
        dim3 grid(O_DIM / 128, BT_DIM / 128);   // (8, 128)
        h_sgemm_kernel<<<grid, 256>>>(x, w, h_ptr);
    }

    // join: scan needs both h and d/invnorm
    cudaStreamWaitEvent(0, evB, 0);
    scan_kernel<<<B_DIM, 256>>>(beta, bvec, spk_dst);

    if (write_loss) finalize_kernel<<<1, 1>>>(out, loss_idx);
}

// round 17
// speedup vs baseline: 1.0481x; 1.0481x over previous
#include <cuda_runtime.h>
#include <cstdint>

// Problem dims (fixed by the dataset)
#define B_DIM 128
#define T_DIM 128
#define I_DIM 1024
#define O_DIM 1024
#define BT_DIM 16384          // B*T
#define BTO_SZ 16777216       // B*T*O
#define IO_SZ  1048576        // I*O

// ---------------- static device scratch (no allocations allowed) ----------------
__device__ float g_h[BTO_SZ];                       // h = x @ w    [B*T, O] fp32
__device__ float g_d[O_DIM * O_DIM];                // d = w^T w    [O, O]
__device__ float g_spk[BTO_SZ];                     // spike scratch (fallback)
__device__ float g_invn[O_DIM];                     // 1/(norm+eps)
__device__ int   g_cnt;

__device__ __forceinline__ uint32_t smem_u32(const void* p) {
    uint32_t a;
    asm("{ .reg .u64 t; cvta.to.shared.u64 t, %1; cvt.u32.u64 %0, t; }" : "=r"(a) : "l"(p));
    return a;
}
#define CP_ASYNC16(dst, src) \
    asm volatile("cp.async.cg.shared.global [%0], [%1], 16;" :: "r"(dst), "l"(src))
#define CP_COMMIT() asm volatile("cp.async.commit_group;")
#define CP_WAIT0()  asm volatile("cp.async.wait_group 0;" ::: "memory")

// ==================== h = x @ w : EXACT R8/R13 kernel (do not touch) ====================
// BITWISE CONTRACT: each output = single fp32 accumulator, IEEE FMA, k ascending.
// At the FFMA2 rt-3 banked ceiling (~680us).
__global__ void __launch_bounds__(256)
h_sgemm_kernel(const float* __restrict__ A,   // x [16384, 1024] row-major
               const float* __restrict__ B,   // w [1024, 1024]  row-major (k-major)
               float* __restrict__ C)
{
    __shared__ __align__(16) float As[2][8][132];   // [stage][k][m]
    __shared__ __align__(16) float Bs[2][8][128];   // [stage][k][n]

    const int tid  = threadIdx.x;
    const int bx   = blockIdx.x;            // N tile (8)
    const int by   = blockIdx.y;            // M tile (128)
    const int trow = tid >> 4;              // 0..15
    const int tcol = tid & 15;              // 0..15

    const int a_row = tid >> 1;
    const int a_k   = (tid & 1) * 4;
    const float* a_src = A + (size_t)(by * 128 + a_row) * I_DIM + a_k;

    const int b_k   = tid >> 5;
    const int b_col = (tid & 31) * 4;
    const float* b_src = B + (size_t)b_k * O_DIM + bx * 128 + b_col;
    const uint32_t bs_dst[2] = { smem_u32(&Bs[0][b_k][b_col]), smem_u32(&Bs[1][b_k][b_col]) };

    unsigned long long acc2[8][4];
#pragma unroll
    for (int i = 0; i < 8; ++i)
#pragma unroll
        for (int j = 0; j < 4; ++j) acc2[i][j] = 0ULL;

    float4 areg = *(const float4*)a_src;
    CP_ASYNC16(bs_dst[0], b_src);
    CP_COMMIT();
    As[0][a_k + 0][a_row] = areg.x;
    As[0][a_k + 1][a_row] = areg.y;
    As[0][a_k + 2][a_row] = areg.z;
    As[0][a_k + 3][a_row] = areg.w;
    CP_WAIT0();
    __syncthreads();

    for (int k0 = 0; k0 < I_DIM; k0 += 8) {
        const int  buf      = (k0 >> 3) & 1;
        const bool has_next = (k0 + 8) < I_DIM;
        if (has_next) {
            areg = *(const float4*)(a_src + k0 + 8);
            CP_ASYNC16(bs_dst[buf ^ 1], b_src + (size_t)(k0 + 8) * O_DIM);
        }
        CP_COMMIT();

#pragma unroll
        for (int kk = 0; kk < 8; ++kk) {
            float a[8];
            *(float4*)&a[0] = *(const float4*)&As[buf][kk][trow * 4];
            *(float4*)&a[4] = *(const float4*)&As[buf][kk][64 + trow * 4];
            const ulonglong2 b01 = *(const ulonglong2*)&Bs[buf][kk][tcol * 4];
            const ulonglong2 b23 = *(const ulonglong2*)&Bs[buf][kk][64 + tcol * 4];
            const unsigned long long b2[4] = { b01.x, b01.y, b23.x, b23.y };
#pragma unroll
            for (int i = 0; i < 8; ++i) {
                unsigned long long a2;
                asm("mov.b64 %0, {%1, %1};" : "=l"(a2) : "f"(a[i]));
#pragma unroll
                for (int j = 0; j < 4; ++j)
                    asm("fma.rn.f32x2 %0, %1, %2, %0;"
                        : "+l"(acc2[i][j]) : "l"(a2), "l"(b2[j]));
            }
        }

        if (has_next) {
            const int nb = buf ^ 1;
            As[nb][a_k + 0][a_row] = areg.x;
            As[nb][a_k + 1][a_row] = areg.y;
            As[nb][a_k + 2][a_row] = areg.z;
            As[nb][a_k + 3][a_row] = areg.w;
        }
        CP_WAIT0();
        __syncthreads();
    }

#pragma unroll
    for (int ih = 0; ih < 2; ++ih)
#pragma unroll
        for (int i = 0; i < 4; ++i) {
            const int m = by * 128 + ih * 64 + trow * 4 + i;
            float* crow = C + (size_t)m * O_DIM + bx * 128;
            const int ai = ih * 4 + i;
            *(ulonglong2*)&crow[tcol * 4]      = make_ulonglong2(acc2[ai][0], acc2[ai][1]);
            *(ulonglong2*)&crow[64 + tcol * 4] = make_ulonglong2(acc2[ai][2], acc2[ai][3]);
        }
}

// ---------------- fp32 tiled GEMM (A^T @ B), used for d = w^T w (unchanged — passed) ----------------
__global__ void sgemm_at_kernel(const float* __restrict__ A,
                                const float* __restrict__ Bm,
                                float* __restrict__ C,
                                int M, int N, int K)
{
    __shared__ float As[8][128];
    __shared__ float Bs[8][128];
    const int tid = threadIdx.x;
    const int bx = blockIdx.x, by = blockIdx.y;
    const int trow = tid / 16, tcol = tid % 16;

    float acc[8][8];
#pragma unroll
    for (int i = 0; i < 8; ++i)
#pragma unroll
        for (int j = 0; j < 8; ++j) acc[i][j] = 0.f;

    for (int k0 = 0; k0 < K; k0 += 8) {
        {
            const int kk = tid >> 5, c4 = (tid & 31) * 4;
            const float4 av = *(const float4*)&A[(size_t)(k0 + kk) * M + by * 128 + c4];
            As[kk][c4 + 0] = av.x; As[kk][c4 + 1] = av.y; As[kk][c4 + 2] = av.z; As[kk][c4 + 3] = av.w;
            const float4 bv = *(const float4*)&Bm[(size_t)(k0 + kk) * N + bx * 128 + c4];
            Bs[kk][c4 + 0] = bv.x; Bs[kk][c4 + 1] = bv.y; Bs[kk][c4 + 2] = bv.z; Bs[kk][c4 + 3] = bv.w;
        }
        __syncthreads();
#pragma unroll
        for (int kk = 0; kk < 8; ++kk) {
            float4 a0 = *(const float4*)&As[kk][trow * 8 + 0];
            float4 a1 = *(const float4*)&As[kk][trow * 8 + 4];
            float4 b0 = *(const float4*)&Bs[kk][tcol * 8 + 0];
            float4 b1 = *(const float4*)&Bs[kk][tcol * 8 + 4];
            float a[8] = {a0.x, a0.y, a0.z, a0.w, a1.x, a1.y, a1.z, a1.w};
            float b[8] = {b0.x, b0.y, b0.z, b0.w, b1.x, b1.y, b1.z, b1.w};
#pragma unroll
            for (int i = 0; i < 8; ++i)
#pragma unroll
                for (int j = 0; j < 8; ++j)
                    acc[i][j] = fmaf(a[i], b[j], acc[i][j]);
        }
        __syncthreads();
    }
#pragma unroll
    for (int i = 0; i < 8; ++i) {
        const size_t r = (size_t)(by * 128 + trow * 8 + i) * N + bx * 128 + tcol * 8;
#pragma unroll
        for (int j = 0; j < 8; j += 4)
            *(float4*)&C[r + j] = make_float4(acc[i][j], acc[i][j + 1], acc[i][j + 2], acc[i][j + 3]);
    }
}

// invnorm + counter reset folded into one launch
__global__ void invnorm_kernel()
{
    const int o = threadIdx.x;
    if (o == 0) g_cnt = 0;
    g_invn[o] = 1.0f / (g_d[(size_t)o * O_DIM + o] + 1e-8f);
}

// ---------------- fused recurrent scan: 256 thr x 4 neurons, MLP-16 LDG.128 gather ----------------
// Latency-bound at MLP-8 (exposure ~ceil(n/8)*260cyc); 16-deep batches halve it.
// BITWISE: per-neuron rst chain = single fp32 accumulator, rows ascending j,
// adds grouped per row; list globally ascending neuron index.
__global__ void __launch_bounds__(256, 1)
scan_kernel(const float* __restrict__ beta_p,
            const float* __restrict__ b_p,
            float* __restrict__ spk_out)
{
    const int b    = blockIdx.x;
    const int tq   = threadIdx.x;          // 0..255
    const int wid  = tq >> 5;              // 0..7
    const int lane = tq & 31;
    const int o0   = tq * 4;               // 4 adjacent neurons per thread

    __shared__ __align__(16) int list[O_DIM];
    __shared__ int warp_cnt[8];

    const float  beta = beta_p[0];
    const float  ombt = 1.0f - beta;
    const float4 invn = *(const float4*)&g_invn[o0];
    const float4 bo   = *(const float4*)&b_p[o0];
    float m0 = 0.f, m1 = 0.f, m2 = 0.f, m3 = 0.f;
    int   n = 0;
    int   tot_spikes = 0;

    const float* __restrict__ hb = g_h + (size_t)b * T_DIM * O_DIM + o0;
    float* __restrict__ sb = spk_out + (size_t)b * T_DIM * O_DIM + o0;

    float4 hcur = *(const float4*)hb;      // prefetch t=0

    for (int t = 0; t < T_DIM; ++t) {
        float4 hnext = make_float4(0.f, 0.f, 0.f, 0.f);
        if (t + 1 < T_DIM) hnext = *(const float4*)(hb + (size_t)(t + 1) * O_DIM);

        float r0 = 0.f, r1 = 0.f, r2 = 0.f, r3 = 0.f;
        int k = 0;
        // 16-deep load batches (double the in-flight LDG.128), adds row-ascending
        for (; k + 16 <= n; k += 16) {
            float4 v[16];
#pragma unroll
            for (int u = 0; u < 16; ++u)
                v[u] = __ldg((const float4*)&g_d[(size_t)list[k + u] * O_DIM + o0]);
#pragma unroll
            for (int u = 0; u < 16; ++u) {
                r0 += v[u].x; r1 += v[u].y; r2 += v[u].z; r3 += v[u].w;
            }
        }
        if (k + 8 <= n) {
            float4 v[8];
#pragma unroll
            for (int u = 0; u < 8; ++u)
                v[u] = __ldg((const float4*)&g_d[(size_t)list[k + u] * O_DIM + o0]);
#pragma unroll
            for (int u = 0; u < 8; ++u) {
                r0 += v[u].x; r1 += v[u].y; r2 += v[u].z; r3 += v[u].w;
            }
            k += 8;
        }
        for (; k < n; ++k) {
            const float4 v = __ldg((const float4*)&g_d[(size_t)list[k] * O_DIM + o0]);
            r0 += v.x; r1 += v.y; r2 += v.z; r3 += v.w;
        }

        m0 = (m0 - r0) * beta + hcur.x * ombt;
        m1 = (m1 - r1) * beta + hcur.y * ombt;
        m2 = (m2 - r2) * beta + hcur.z * ombt;
        m3 = (m3 - r3) * beta + hcur.w * ombt;
        hcur = hnext;

        const bool s0 = (m0 * invn.x - bo.x) > 0.0f;
        const bool s1 = (m1 * invn.y - bo.y) > 0.0f;
        const bool s2 = (m2 * invn.z - bo.z) > 0.0f;
        const bool s3 = (m3 * invn.w - bo.w) > 0.0f;
        *(float4*)(sb + (size_t)t * O_DIM) =
            make_float4(s0 ? 1.f : 0.f, s1 ? 1.f : 0.f, s2 ? 1.f : 0.f, s3 ? 1.f : 0.f);

        const unsigned q0 = __ballot_sync(0xffffffffu, s0);
        const unsigned q1 = __ballot_sync(0xffffffffu, s1);
        const unsigned q2 = __ballot_sync(0xffffffffu, s2);
        const unsigned q3 = __ballot_sync(0xffffffffu, s3);
        if (lane == 0)
            warp_cnt[wid] = __popc(q0) + __popc(q1) + __popc(q2) + __popc(q3);
        __syncthreads();   // counts visible; separates list reads from writes

        int x = (lane < 8) ? warp_cnt[lane] : 0;
#pragma unroll
        for (int dlt = 1; dlt < 8; dlt <<= 1) {
            int y = __shfl_up_sync(0xffffffffu, x, dlt);
            if (lane >= dlt) x += y;
        }
        const int total = __shfl_sync(0xffffffffu, x, 7);
        const int off   = (wid == 0) ? 0 : __shfl_sync(0xffffffffu, x, wid - 1);

        const unsigned lt = (1u << lane) - 1u;
        int p = off + __popc(q0 & lt) + __popc(q1 & lt) + __popc(q2 & lt) + __popc(q3 & lt);
        if (s0) list[p++] = o0;
        if (s1) list[p++] = o0 + 1;
        if (s2) list[p++] = o0 + 2;
        if (s3) list[p]   = o0 + 3;

        n = total;
        if (tq == 0) tot_spikes += total;
        __syncthreads();   // list ready for next step
    }

    if (tq == 0) atomicAdd(&g_cnt, tot_spikes);
}

__global__ void finalize_kernel(float* out, int loss_idx)
{
    out[loss_idx] = 0.5f * (float)g_cnt / (float)BTO_SZ;
}

// ==================== host side ====================
extern "C" void kernel_launch(void* const* d_in, const int* in_sizes, int n_in,
                              void* d_out, int out_size)
{
    const float *x = nullptr, *w = nullptr, *beta = nullptr, *bvec = nullptr;
    for (int i = 0; i < n_in; ++i) {
        switch (in_sizes[i]) {
            case BTO_SZ:  x    = (const float*)d_in[i]; break;
            case IO_SZ:   w    = (const float*)d_in[i]; break;
            case 1:       beta = (const float*)d_in[i]; break;
            case O_DIM:   bvec = (const float*)d_in[i]; break;
            default: break;
        }
    }

    float* out = (float*)d_out;
    float* spk_dst;
    bool   write_loss;
    int    loss_idx = 0;
    if (out_size >= BTO_SZ + 1) {
        spk_dst = out; write_loss = true; loss_idx = BTO_SZ;
    } else if (out_size == BTO_SZ) {
        spk_dst = out; write_loss = false;
    } else {
        void* p = nullptr; cudaGetSymbolAddress(&p, g_spk);
        spk_dst = (float*)p; write_loss = true; loss_idx = (out_size > 0) ? out_size - 1 : 0;
    }

    float* h_ptr; { void* p; cudaGetSymbolAddress(&p, g_h); h_ptr = (float*)p; }
    float* d_ptr; { void* p; cudaGetSymbolAddress(&p, g_d); d_ptr = (float*)p; }

    // one-time side-stream resources (created on the first, non-captured call)
    static cudaStream_t s2 = nullptr;
    static cudaEvent_t  evA = nullptr, evB = nullptr;
    if (!s2) {
        cudaStreamCreateWithFlags(&s2, cudaStreamNonBlocking);
        cudaEventCreateWithFlags(&evA, cudaEventDisableTiming);
        cudaEventCreateWithFlags(&evB, cudaEventDisableTiming);
    }

    // fork: d = w^T w (+ invnorm/counter reset) on side stream, concurrent with h
    cudaEventRecord(evA, 0);
    cudaStreamWaitEvent(s2, evA, 0);
    {
        dim3 grid(O_DIM / 128, O_DIM / 128);    // 64 CTAs — fills h's tail waves
        sgemm_at_kernel<<<grid, 256, 0, s2>>>(w, w, d_ptr, O_DIM, O_DIM, I_DIM);
    }
    invnorm_kernel<<<1, O_DIM, 0, s2>>>();
    cudaEventRecord(evB, s2);

    // h = x @ w : EXACT R8/R13 winner (FFMA2 ceiling), main stream
    {
        dim3 grid(O_DIM / 128, BT_DIM / 128);   // (8, 128)
        h_sgemm_kernel<<<grid, 256>>>(x, w, h_ptr);
    }

    // join: scan needs both h and d/invnorm
    cudaStreamWaitEvent(0, evB, 0);
    scan_kernel<<<B_DIM, 256>>>(beta, bvec, spk_dst);

    if (write_loss) finalize_kernel<<<1, 1>>>(out, loss_idx);
}